// round 12
// baseline (speedup 1.0000x reference)
#include <cuda_runtime.h>
#include <cuda_fp16.h>
#include <math_constants.h>

// Tropical (max-plus) depthwise 5x5 conv, stride=1, pad=2, dil=1.
// x: [8,32,224,224] f32; kernel: [32,1,5,5] f32; out: f32 same shape.
// fp16x2 core (HADD2+HMNMX2, tree maxes). R9: PLANE PAIRING — each thread
// computes the same (y,x) tile for two batch images of the same channel
// (identical weights), doubling per-warp ILP/MLP at shared addressing cost.

#define TC_H 224
#define TC_W 224
#define TC_C 32
#define TC_TY 4   // output rows per thread; 4 cols per thread; 2 planes

__global__ __launch_bounds__(224, 4)
void tropical_conv_h2_kernel(const float* __restrict__ x,
                             const float* __restrict__ ker,
                             float* __restrict__ out)
{
    const int tid = threadIdx.x;           // 0..223 (7 full warps)
    const int tx  = tid % 56;              // column lane
    const int sub = tid / 56;              // row subtile 0..3
    const int x0  = tx * 4;                // output column base (0..220)
    const int gy  = blockIdx.y;            // 0..127: c + 32*bpair
    const int c   = gy & (TC_C - 1);
    const int b0  = (gy >> 5) * 2;         // batches b0, b0+1
    const int planeA = b0 * TC_C + c;
    const int planeB = planeA + TC_C;      // next batch, same channel
    const int y0 = (blockIdx.x * 4 + sub) * TC_TY;   // 14*4*4 = 224 rows

    const float* __restrict__ xa = x + (size_t)planeA * (TC_H * TC_W);
    const float* __restrict__ xb = x + (size_t)planeB * (TC_H * TC_W);
    float* __restrict__ oa = out + (size_t)planeA * (TC_H * TC_W);
    float* __restrict__ ob = out + (size_t)planeB * (TC_H * TC_W);

    // Weights as broadcast half2 (shared by both planes).
    half2 w2[5][5];
    const float* kc = ker + c * 25;
#pragma unroll
    for (int i = 0; i < 5; i++)
#pragma unroll
        for (int j = 0; j < 5; j++)
            w2[i][j] = __float2half2_rn(__ldg(kc + i * 5 + j));

    const float NEGF = -CUDART_INF_F;
    const half2 NEG2 = __float2half2_rn(NEGF);

    half2 accA[TC_TY][2], accB[TC_TY][2];
#pragma unroll
    for (int yy = 0; yy < TC_TY; yy++) {
        accA[yy][0] = NEG2; accA[yy][1] = NEG2;
        accB[yy][0] = NEG2; accB[yy][1] = NEG2;
    }

    // Stream input rows r = y0-2 .. y0+TY+1 for BOTH planes (fully unrolled).
#pragma unroll
    for (int rr = 0; rr < TC_TY + 4; rr++) {
        const int r = y0 - 2 + rr;
        float a0,a1,a2,a3,a4,a5,a6,a7;      // plane A, cols x0-2..x0+5
        float b0f,b1f,b2f,b3f,b4f,b5f,b6f,b7f; // plane B
        if ((unsigned)r < (unsigned)TC_H) {
            const float* rowA = xa + r * TC_W;
            const float* rowB = xb + r * TC_W;
            float4 mA = *reinterpret_cast<const float4*>(rowA + x0);
            float4 mB = *reinterpret_cast<const float4*>(rowB + x0);
            a2 = mA.x; a3 = mA.y; a4 = mA.z; a5 = mA.w;
            b2f = mB.x; b3f = mB.y; b4f = mB.z; b5f = mB.w;
            if (x0 > 0) {
                float2 lA = *reinterpret_cast<const float2*>(rowA + x0 - 2);
                float2 lB = *reinterpret_cast<const float2*>(rowB + x0 - 2);
                a0 = lA.x; a1 = lA.y; b0f = lB.x; b1f = lB.y;
            } else { a0 = a1 = NEGF; b0f = b1f = NEGF; }
            if (x0 < TC_W - 4) {
                float2 rA = *reinterpret_cast<const float2*>(rowA + x0 + 4);
                float2 rB = *reinterpret_cast<const float2*>(rowB + x0 + 4);
                a6 = rA.x; a7 = rA.y; b6f = rB.x; b7f = rB.y;
            } else { a6 = a7 = NEGF; b6f = b7f = NEGF; }
        } else {
            a0=a1=a2=a3=a4=a5=a6=a7=NEGF;
            b0f=b1f=b2f=b3f=b4f=b5f=b6f=b7f=NEGF;
        }

        // Pack both planes: aligned v, shifted s (F2FP).
        half2 Av0 = __floats2half2_rn(a0, a1), Bv0 = __floats2half2_rn(b0f, b1f);
        half2 Av1 = __floats2half2_rn(a2, a3), Bv1 = __floats2half2_rn(b2f, b3f);
        half2 Av2 = __floats2half2_rn(a4, a5), Bv2 = __floats2half2_rn(b4f, b5f);
        half2 Av3 = __floats2half2_rn(a6, a7), Bv3 = __floats2half2_rn(b6f, b7f);
        half2 As01 = __floats2half2_rn(a1, a2), Bs01 = __floats2half2_rn(b1f, b2f);
        half2 As12 = __floats2half2_rn(a3, a4), Bs12 = __floats2half2_rn(b3f, b4f);
        half2 As23 = __floats2half2_rn(a5, a6), Bs23 = __floats2half2_rn(b5f, b6f);

#pragma unroll
        for (int yy = 0; yy < TC_TY; yy++) {
            const int ki = yy - rr + 4;    // compile-time after unroll
            if (ki < 0 || ki > 4) continue;
            const half2 k0 = w2[ki][4], k1 = w2[ki][3], k2 = w2[ki][2];
            const half2 k3 = w2[ki][1], k4 = w2[ki][0];
            // Plane A, acc0 (c0,c1)
            {
                half2 c0 = __hadd2(Av0,  k0), c1 = __hadd2(As01, k1);
                half2 c2 = __hadd2(Av1,  k2), c3 = __hadd2(As12, k3);
                half2 c4 = __hadd2(Av2,  k4);
                half2 t = __hmax2(__hmax2(__hmax2(c0,c1), __hmax2(c2,c3)), c4);
                accA[yy][0] = __hmax2(accA[yy][0], t);
            }
            // Plane A, acc1 (c2,c3)
            {
                half2 c0 = __hadd2(Av1,  k0), c1 = __hadd2(As12, k1);
                half2 c2 = __hadd2(Av2,  k2), c3 = __hadd2(As23, k3);
                half2 c4 = __hadd2(Av3,  k4);
                half2 t = __hmax2(__hmax2(__hmax2(c0,c1), __hmax2(c2,c3)), c4);
                accA[yy][1] = __hmax2(accA[yy][1], t);
            }
            // Plane B, acc0
            {
                half2 c0 = __hadd2(Bv0,  k0), c1 = __hadd2(Bs01, k1);
                half2 c2 = __hadd2(Bv1,  k2), c3 = __hadd2(Bs12, k3);
                half2 c4 = __hadd2(Bv2,  k4);
                half2 t = __hmax2(__hmax2(__hmax2(c0,c1), __hmax2(c2,c3)), c4);
                accB[yy][0] = __hmax2(accB[yy][0], t);
            }
            // Plane B, acc1
            {
                half2 c0 = __hadd2(Bv1,  k0), c1 = __hadd2(Bs12, k1);
                half2 c2 = __hadd2(Bv2,  k2), c3 = __hadd2(Bs23, k3);
                half2 c4 = __hadd2(Bv3,  k4);
                half2 t = __hmax2(__hmax2(__hmax2(c0,c1), __hmax2(c2,c3)), c4);
                accB[yy][1] = __hmax2(accB[yy][1], t);
            }
        }
    }

#pragma unroll
    for (int yy = 0; yy < TC_TY; yy++) {
        const int y = y0 + yy;
        float2 al = __half22float2(accA[yy][0]);
        float2 ah = __half22float2(accA[yy][1]);
        float2 bl = __half22float2(accB[yy][0]);
        float2 bh = __half22float2(accB[yy][1]);
        float4 ra; ra.x = al.x; ra.y = al.y; ra.z = ah.x; ra.w = ah.y;
        float4 rb; rb.x = bl.x; rb.y = bl.y; rb.z = bh.x; rb.w = bh.y;
        *reinterpret_cast<float4*>(oa + y * TC_W + x0) = ra;
        *reinterpret_cast<float4*>(ob + y * TC_W + x0) = rb;
    }
}

extern "C" void kernel_launch(void* const* d_in, const int* in_sizes, int n_in,
                              void* d_out, int out_size)
{
    const float* x = (const float*)d_in[0];     // [8,32,224,224]
    const float* k = (const float*)d_in[1];     // [32,1,5,5]
    float* out = (float*)d_out;

    dim3 block(224, 1, 1);
    dim3 grid(14, 128, 1);                      // rows: 14*4*4=224; 128 plane-pairs
    tropical_conv_h2_kernel<<<grid, block>>>(x, k, out);
}

// round 14
// speedup vs baseline: 1.3855x; 1.3855x over previous
#include <cuda_runtime.h>
#include <cuda_fp16.h>
#include <math_constants.h>

// Tropical (max-plus) depthwise 5x5 conv, stride=1, pad=2, dil=1.
// x: [8,32,224,224] f32; kernel: [32,1,5,5] f32; out: f32 same shape.
// R13: smem-staged tile. CTA bulk-loads 20 input rows (fp32, MLP=5/thread),
// converts to fp16 ONCE per element, stores with 2-col NEG halo into smem.
// Inner loop reads half2 windows via LDS (29cyc vs ~250cyc L2) + PRMT shifts.
// Core compute: HADD2 + HMNMX2 tree maxes, 25 packed ops / output (floor).

#define TC_H 224
#define TC_W 224
#define TC_C 32
#define TC_TY 4        // output rows per thread (CTA: 16 rows x 224 cols)
#define SM_ROWS 20     // 16 + 4 halo
#define SM_STRIDE 232  // 2 pad + 224 + 2 pad, rounded up

static __device__ __forceinline__ unsigned h2u(half2 v) {
    return *reinterpret_cast<unsigned*>(&v);
}
static __device__ __forceinline__ half2 u2h(unsigned u) {
    return *reinterpret_cast<half2*>(&u);
}

__global__ __launch_bounds__(224, 5)
void tropical_conv_smem_kernel(const float* __restrict__ x,
                               const float* __restrict__ ker,
                               float* __restrict__ out)
{
    __shared__ half smh[SM_ROWS][SM_STRIDE];

    const int tid = threadIdx.x;           // 0..223 (7 full warps)
    const int tx  = tid % 56;              // column lane
    const int sub = tid / 56;              // row subtile 0..3
    const int x0  = tx * 4;                // output column base (0..220)
    const int plane = blockIdx.y;          // b*32 + c
    const int c = plane & (TC_C - 1);
    const int y0 = blockIdx.x * 16;        // CTA output row base (14*16 = 224)

    const float* __restrict__ xp = x + (size_t)plane * (TC_H * TC_W);
    float* __restrict__ op = out + (size_t)plane * (TC_H * TC_W);

    const float NEGF = -CUDART_INF_F;
    const half2 NEG2 = __float2half2_rn(NEGF);

    // ---- Cooperative fill: 20 rows x 224 cols, fp32 -> fp16, padded ----
    // 20*56 = 1120 float4 tasks; 224 threads -> exactly 5 each (independent LDGs).
#pragma unroll
    for (int it = 0; it < 5; it++) {
        const int idx = tid + it * 224;
        const int srow = idx / 56;
        const int c4 = (idx % 56) * 4;
        const int r = y0 - 2 + srow;
        half2 lo = NEG2, hi = NEG2;
        if ((unsigned)r < (unsigned)TC_H) {
            float4 m = *reinterpret_cast<const float4*>(xp + r * TC_W + c4);
            lo = __floats2half2_rn(m.x, m.y);
            hi = __floats2half2_rn(m.z, m.w);
        }
        *reinterpret_cast<half2*>(&smh[srow][2 + c4])     = lo;
        *reinterpret_cast<half2*>(&smh[srow][2 + c4 + 2]) = hi;
    }
    // Side pads: cols {0,1} and {226,227} for all 20 rows.
    if (tid < 40) {
        const int srow = tid >> 1;
        if (tid & 1) *reinterpret_cast<half2*>(&smh[srow][226]) = NEG2;
        else         *reinterpret_cast<half2*>(&smh[srow][0])   = NEG2;
    }

    // Weights as broadcast half2 (L1-broadcast across block).
    half2 w2[5][5];
    const float* kc = ker + c * 25;
#pragma unroll
    for (int i = 0; i < 5; i++)
#pragma unroll
        for (int j = 0; j < 5; j++)
            w2[i][j] = __float2half2_rn(__ldg(kc + i * 5 + j));

    __syncthreads();

    // ---- Register compute: TY=4 rows x 4 cols per thread ----
    half2 acc[TC_TY][2];
#pragma unroll
    for (int yy = 0; yy < TC_TY; yy++) {
        acc[yy][0] = NEG2;
        acc[yy][1] = NEG2;
    }

#pragma unroll
    for (int rr = 0; rr < TC_TY + 4; rr++) {
        const int s = sub * TC_TY + rr;    // smem row (input row y0-2+s)
        // smem col x0 holds input col x0-2; read 8 halves x0-2..x0+5.
        const half2* rowp = reinterpret_cast<const half2*>(&smh[s][x0]);
        half2 v0 = rowp[0];                // (c-2,c-1)
        half2 v1 = rowp[1];                // (c0,c1)
        half2 v2 = rowp[2];                // (c2,c3)
        half2 v3 = rowp[3];                // (c4,c5)
        unsigned u0 = h2u(v0), u1 = h2u(v1), u2 = h2u(v2), u3 = h2u(v3);
        half2 s01 = u2h(__byte_perm(u0, u1, 0x5432)); // (c-1,c0)
        half2 s12 = u2h(__byte_perm(u1, u2, 0x5432)); // (c1,c2)
        half2 s23 = u2h(__byte_perm(u2, u3, 0x5432)); // (c3,c4)

#pragma unroll
        for (int yy = 0; yy < TC_TY; yy++) {
            const int ki = yy - rr + 4;    // compile-time after unroll
            if (ki < 0 || ki > 4) continue;
            const half2 k0 = w2[ki][4], k1 = w2[ki][3], k2 = w2[ki][2];
            const half2 k3 = w2[ki][1], k4 = w2[ki][0];
            // acc0 covers (c0,c1): windows v0,s01,v1,s12,v2
            {
                half2 c0 = __hadd2(v0,  k0), c1 = __hadd2(s01, k1);
                half2 c2 = __hadd2(v1,  k2), c3 = __hadd2(s12, k3);
                half2 c4 = __hadd2(v2,  k4);
                half2 t = __hmax2(__hmax2(__hmax2(c0, c1), __hmax2(c2, c3)), c4);
                acc[yy][0] = __hmax2(acc[yy][0], t);
            }
            // acc1 covers (c2,c3): windows v1,s12,v2,s23,v3
            {
                half2 c0 = __hadd2(v1,  k0), c1 = __hadd2(s12, k1);
                half2 c2 = __hadd2(v2,  k2), c3 = __hadd2(s23, k3);
                half2 c4 = __hadd2(v3,  k4);
                half2 t = __hmax2(__hmax2(__hmax2(c0, c1), __hmax2(c2, c3)), c4);
                acc[yy][1] = __hmax2(acc[yy][1], t);
            }
        }
    }

#pragma unroll
    for (int yy = 0; yy < TC_TY; yy++) {
        const int y = y0 + sub * TC_TY + yy;
        float2 lo = __half22float2(acc[yy][0]);
        float2 hi = __half22float2(acc[yy][1]);
        float4 o; o.x = lo.x; o.y = lo.y; o.z = hi.x; o.w = hi.y;
        *reinterpret_cast<float4*>(op + y * TC_W + x0) = o;
    }
}

extern "C" void kernel_launch(void* const* d_in, const int* in_sizes, int n_in,
                              void* d_out, int out_size)
{
    const float* x = (const float*)d_in[0];     // [8,32,224,224]
    const float* k = (const float*)d_in[1];     // [32,1,5,5]
    float* out = (float*)d_out;

    dim3 block(224, 1, 1);
    dim3 grid(14, 256, 1);                      // 14 chunks of 16 rows; 256 planes
    tropical_conv_smem_kernel<<<grid, block>>>(x, k, out);
}

// round 16
// speedup vs baseline: 1.5208x; 1.0977x over previous
#include <cuda_runtime.h>
#include <cuda_fp16.h>
#include <math_constants.h>

// Tropical (max-plus) depthwise 5x5 conv, stride=1, pad=2, dil=1.
// x: [8,32,224,224] f32; kernel: [32,1,5,5] f32; out: f32 same shape.
// R15: smem-staged fp16 tile (R13) + 8-wide thread columns (R7).
// CTA = 32 output rows x 224 cols; smem 36 rows x 232 halves (2-col NEG halo).
// Inner loop: LDS.128+LDS.64 per row window, PRMT shifts, HADD2+HMNMX2 tree.

#define TC_H 224
#define TC_W 224
#define TC_C 32
#define TC_TY 4        // output rows per thread; 8 cols per thread
#define CTA_ROWS 32    // 8 subtiles * TY
#define SM_ROWS 36     // 32 + 4 halo
#define SM_STRIDE 232  // 2 pad + 224 + 2 pad

static __device__ __forceinline__ unsigned h2u(half2 v) {
    return *reinterpret_cast<unsigned*>(&v);
}
static __device__ __forceinline__ half2 u2h(unsigned u) {
    return *reinterpret_cast<half2*>(&u);
}

__global__ __launch_bounds__(224, 4)
void tropical_conv_smem8_kernel(const float* __restrict__ x,
                                const float* __restrict__ ker,
                                float* __restrict__ out)
{
    __shared__ half smh[SM_ROWS][SM_STRIDE];

    const int tid = threadIdx.x;           // 0..223 (7 full warps)
    const int tx  = tid % 28;              // column lane: 28*8 = 224 cols
    const int sub = tid / 28;              // row subtile 0..7
    const int x0  = tx * 8;                // output column base (0..216)
    const int plane = blockIdx.y;          // b*32 + c
    const int c = plane & (TC_C - 1);
    const int y0 = blockIdx.x * CTA_ROWS;  // 7*32 = 224 rows

    const float* __restrict__ xp = x + (size_t)plane * (TC_H * TC_W);
    float* __restrict__ op = out + (size_t)plane * (TC_H * TC_W);

    const float NEGF = -CUDART_INF_F;
    const half2 NEG2 = __float2half2_rn(NEGF);

    // Weights first (independent LDGs overlap with fill loads below).
    half2 w2[5][5];
    const float* kc = ker + c * 25;
#pragma unroll
    for (int i = 0; i < 5; i++)
#pragma unroll
        for (int j = 0; j < 5; j++)
            w2[i][j] = __float2half2_rn(__ldg(kc + i * 5 + j));

    // ---- Cooperative fill: 36 rows x 224 cols, fp32 -> fp16, padded ----
    // 36*56 = 2016 float4 tasks; 224 threads -> exactly 9 each.
#pragma unroll
    for (int it = 0; it < 9; it++) {
        const int idx = tid + it * 224;
        const int srow = idx / 56;
        const int c4 = (idx % 56) * 4;
        const int r = y0 - 2 + srow;
        half2 lo = NEG2, hi = NEG2;
        if ((unsigned)r < (unsigned)TC_H) {
            float4 m = *reinterpret_cast<const float4*>(xp + r * TC_W + c4);
            lo = __floats2half2_rn(m.x, m.y);
            hi = __floats2half2_rn(m.z, m.w);
        }
        *reinterpret_cast<half2*>(&smh[srow][2 + c4])     = lo;
        *reinterpret_cast<half2*>(&smh[srow][2 + c4 + 2]) = hi;
    }
    // Side pads: cols {0,1} and {226,227} for all 36 rows (72 half2 writes).
    if (tid < 72) {
        const int srow = tid >> 1;
        if (tid & 1) *reinterpret_cast<half2*>(&smh[srow][226]) = NEG2;
        else         *reinterpret_cast<half2*>(&smh[srow][0])   = NEG2;
    }

    __syncthreads();

    // ---- Register compute: TY=4 rows x 8 cols per thread ----
    half2 acc[TC_TY][4];
#pragma unroll
    for (int yy = 0; yy < TC_TY; yy++)
#pragma unroll
        for (int a = 0; a < 4; a++)
            acc[yy][a] = NEG2;

#pragma unroll
    for (int rr = 0; rr < TC_TY + 4; rr++) {
        const int s = sub * TC_TY + rr;    // smem row (input row y0-2+s)
        // smem col x0 holds input col x0-2; need 12 halves x0-2..x0+9.
        // Base is 16B-aligned (x0*2 = 16*tx, row stride 464B) -> LDS.128+LDS.64.
        const half2* rowp = reinterpret_cast<const half2*>(&smh[s][x0]);
        half2 v0 = rowp[0];                // (c-2,c-1)
        half2 v1 = rowp[1];                // (c0,c1)
        half2 v2 = rowp[2];                // (c2,c3)
        half2 v3 = rowp[3];                // (c4,c5)
        half2 v4 = rowp[4];                // (c6,c7)
        half2 v5 = rowp[5];                // (c8,c9)
        unsigned u0 = h2u(v0), u1 = h2u(v1), u2 = h2u(v2);
        unsigned u3 = h2u(v3), u4 = h2u(v4), u5 = h2u(v5);
        half2 s01 = u2h(__byte_perm(u0, u1, 0x5432)); // (c-1,c0)
        half2 s12 = u2h(__byte_perm(u1, u2, 0x5432)); // (c1,c2)
        half2 s23 = u2h(__byte_perm(u2, u3, 0x5432)); // (c3,c4)
        half2 s34 = u2h(__byte_perm(u3, u4, 0x5432)); // (c5,c6)
        half2 s45 = u2h(__byte_perm(u4, u5, 0x5432)); // (c7,c8)

        // Window sets per acc a (cols 2a,2a+1), kj = 4..0:
        half2 W0[4] = { v0,  v1,  v2,  v3  };
        half2 W1[4] = { s01, s12, s23, s34 };
        half2 W2[4] = { v1,  v2,  v3,  v4  };
        half2 W3[4] = { s12, s23, s34, s45 };
        half2 W4[4] = { v2,  v3,  v4,  v5  };

#pragma unroll
        for (int yy = 0; yy < TC_TY; yy++) {
            const int ki = yy - rr + 4;    // compile-time after unroll
            if (ki < 0 || ki > 4) continue;
            const half2 k0 = w2[ki][4], k1 = w2[ki][3], k2 = w2[ki][2];
            const half2 k3 = w2[ki][1], k4 = w2[ki][0];
#pragma unroll
            for (int a = 0; a < 4; a++) {
                half2 c0 = __hadd2(W0[a], k0);
                half2 c1 = __hadd2(W1[a], k1);
                half2 c2 = __hadd2(W2[a], k2);
                half2 c3 = __hadd2(W3[a], k3);
                half2 c4 = __hadd2(W4[a], k4);
                half2 t = __hmax2(__hmax2(__hmax2(c0, c1), __hmax2(c2, c3)), c4);
                acc[yy][a] = __hmax2(acc[yy][a], t);
            }
        }
    }

#pragma unroll
    for (int yy = 0; yy < TC_TY; yy++) {
        const int y = y0 + sub * TC_TY + yy;
        float2 p0 = __half22float2(acc[yy][0]);
        float2 p1 = __half22float2(acc[yy][1]);
        float2 p2 = __half22float2(acc[yy][2]);
        float2 p3 = __half22float2(acc[yy][3]);
        float4 o0; o0.x = p0.x; o0.y = p0.y; o0.z = p1.x; o0.w = p1.y;
        float4 o1; o1.x = p2.x; o1.y = p2.y; o1.z = p3.x; o1.w = p3.y;
        *reinterpret_cast<float4*>(op + y * TC_W + x0)     = o0;
        *reinterpret_cast<float4*>(op + y * TC_W + x0 + 4) = o1;
    }
}

extern "C" void kernel_launch(void* const* d_in, const int* in_sizes, int n_in,
                              void* d_out, int out_size)
{
    const float* x = (const float*)d_in[0];     // [8,32,224,224]
    const float* k = (const float*)d_in[1];     // [32,1,5,5]
    float* out = (float*)d_out;

    dim3 block(224, 1, 1);
    dim3 grid(7, 256, 1);                       // 7 chunks of 32 rows; 256 planes
    tropical_conv_smem8_kernel<<<grid, block>>>(x, k, out);
}